// round 1
// baseline (speedup 1.0000x reference)
#include <cuda_runtime.h>
#include <math.h>

#define NBATCH 2
#define SEQ 2048
#define TT (NBATCH*SEQ)      /* 4096 tokens */
#define DIM 1024
#define NH 16
#define NKV 4
#define HD 64
#define KVD (NKV*HD)         /* 256 */
#define NE 8
#define HID 2816
#define VOCAB 32000
#define NL 2
#define EPSF 1e-6f
#define MAXT 72              /* max row-tiles across all expert segments: 8192/128 + 8 */

// ------------------------- scratch (device globals, no allocs) -------------
__device__ float g_h [TT*DIM];
__device__ float g_xn[TT*DIM];
__device__ float g_q [TT*DIM];
__device__ float g_k [TT*KVD];
__device__ float g_v [TT*KVD];
__device__ float g_ao[TT*DIM];
__device__ float g_b1[TT*2*HID];
__device__ float g_b3[TT*2*HID];
__device__ int   g_tope[TT*2];
__device__ float g_topw[TT*2];
__device__ int   g_cnt[NE];
__device__ int   g_scnt[NE];
__device__ int   g_seg[NE];
__device__ int   g_perm[TT*2];
__device__ float g_pwgt[TT*2];
__device__ int   g_te[MAXT], g_tp[MAXT], g_tv[MAXT];

__device__ __forceinline__ float* bufsel(int id){
    switch(id){
        case 0: return g_h;
        case 1: return g_xn;
        case 2: return g_q;
        case 3: return g_k;
        case 4: return g_v;
        case 5: return g_ao;
        case 6: return g_b1;
        default: return g_b3;
    }
}

// ------------------------- embedding gather --------------------------------
__global__ void embed_k(const int* __restrict__ tok, const float* __restrict__ emb){
    int i = blockIdx.x*256 + threadIdx.x;          // over TT*(DIM/4)
    int t = i >> 8;                                 // DIM/4 = 256
    int d = (i & 255) * 4;
    int id = tok[t];
    *(float4*)&g_h[(size_t)t*DIM + d] = *(const float4*)&emb[(size_t)id*DIM + d];
}

// ------------------------- rmsnorm: g_h -> g_xn ----------------------------
__global__ void rms_k(const float* __restrict__ w){
    int t = blockIdx.x, tid = threadIdx.x;
    const float* xr = g_h + (size_t)t*DIM;
    float s = 0.f;
    for(int i = tid; i < DIM; i += 256){ float v = xr[i]; s += v*v; }
#pragma unroll
    for(int o=16;o;o>>=1) s += __shfl_xor_sync(0xffffffffu, s, o);
    __shared__ float sm[8];
    if((tid&31)==0) sm[tid>>5] = s;
    __syncthreads();
    if(tid==0){
        float tot = 0.f;
#pragma unroll
        for(int i=0;i<8;i++) tot += sm[i];
        sm[0] = rsqrtf(tot/DIM + EPSF);
    }
    __syncthreads();
    float inv = sm[0];
    float* o = g_xn + (size_t)t*DIM;
    for(int i = tid; i < DIM; i += 256) o[i] = xr[i]*inv*w[i];
}

// ------------------------- generic SGEMM 128x128x16 ------------------------
// MODE 0: C = A@B    MODE 1: C += A@B
template<int MODE>
__global__ __launch_bounds__(256) void sgemm_k(int aid, const float* __restrict__ Bm,
                                               float* Cext, int cid,
                                               int M, int N, int K)
{
    const float* A = bufsel(aid);
    float* C = (cid >= 0) ? bufsel(cid) : Cext;
    __shared__ float As[16][128];
    __shared__ float Bs[16][128];
    const int tid = threadIdx.x;
    const int bm = blockIdx.y*128, bn = blockIdx.x*128;
    const int ty = tid>>4, tx = tid&15;
    float acc[8][8];
#pragma unroll
    for(int i=0;i<8;i++)
#pragma unroll
        for(int j=0;j<8;j++) acc[i][j]=0.f;

    for(int k0=0;k0<K;k0+=16){
#pragma unroll
        for(int u=0;u<2;u++){
            int s = tid*2+u;
            int r = s>>2, kk = (s&3)*4;
            int gr = bm + r;
            float4 av = make_float4(0.f,0.f,0.f,0.f);
            if(gr < M) av = *(const float4*)(A + (size_t)gr*K + k0 + kk);
            As[kk+0][r]=av.x; As[kk+1][r]=av.y; As[kk+2][r]=av.z; As[kk+3][r]=av.w;
            int br = s>>5, bc = (s&31)*4;
            *(float4*)&Bs[br][bc] = *(const float4*)(Bm + (size_t)(k0+br)*N + bn + bc);
        }
        __syncthreads();
#pragma unroll
        for(int kk=0;kk<16;kk++){
            float4 a0=*(const float4*)&As[kk][ty*4];
            float4 a1=*(const float4*)&As[kk][ty*4+64];
            float4 b0=*(const float4*)&Bs[kk][tx*4];
            float4 b1=*(const float4*)&Bs[kk][tx*4+64];
            float a[8]={a0.x,a0.y,a0.z,a0.w,a1.x,a1.y,a1.z,a1.w};
            float b[8]={b0.x,b0.y,b0.z,b0.w,b1.x,b1.y,b1.z,b1.w};
#pragma unroll
            for(int i=0;i<8;i++)
#pragma unroll
                for(int j=0;j<8;j++) acc[i][j] += a[i]*b[j];
        }
        __syncthreads();
    }
#pragma unroll
    for(int i=0;i<8;i++){
        int lr = (i<4)? ty*4+i : 64+ty*4+(i-4);
        int gr = bm + lr;
        if(gr >= M) continue;
#pragma unroll
        for(int j=0;j<8;j++){
            int lc = (j<4)? tx*4+j : 64+tx*4+(j-4);
            size_t off = (size_t)gr*N + bn + lc;
            if(MODE==0) C[off] = acc[i][j];
            else        C[off] += acc[i][j];
        }
    }
}

// ------------------------- RoPE --------------------------------------------
__global__ void rope_k(int id, int nh, const int* __restrict__ sp){
    int i = blockIdx.x*256 + threadIdx.x;   // over TT*nh*(HD/2)
    if(i >= TT*nh*(HD/2)) return;
    int p = i & 31;
    int rest = i >> 5;
    int hh = rest % nh;
    int t  = rest / nh;
    int pos = sp[0] + (t % SEQ);
    float inv = (float)exp(-((double)(2*p)/(double)HD) * log(10000.0));
    float ang = (float)pos * inv;
    float s, c;
    sincosf(ang, &s, &c);
    float* base = bufsel(id) + ((size_t)t*nh + hh)*HD + 2*p;
    float x1 = base[0], x2 = base[1];
    base[0] = x1*c - x2*s;
    base[1] = x1*s + x2*c;
}

// ------------------------- flash attention (fp32) --------------------------
// grid: (SEQ/64, NH, NBATCH), 256 threads. Q tile 64x64, K/V tiles 32.
__global__ __launch_bounds__(256) void attn_k(){
    __shared__ float sQ [64*64];   // 16 KB
    __shared__ float sKP[64*32];   // 8 KB  (K^T, reused for P)
    __shared__ float sV [32*64];   // 8 KB
    const int qt = blockIdx.x, h = blockIdx.y, b = blockIdx.z;
    const int tid = threadIdx.x, ty = tid>>4, tx = tid&15;
    const int kvh = h >> 2;

#pragma unroll
    for(int u=0;u<4;u++){
        int s4 = u*256 + tid;
        int r = s4>>4, d = (s4&15)*4;
        float4 v = *(const float4*)(g_q + ((size_t)(b*SEQ + qt*64 + r))*DIM + h*HD + d);
        v.x*=0.125f; v.y*=0.125f; v.z*=0.125f; v.w*=0.125f;
        *(float4*)&sQ[r*64+d] = v;
    }
    float O[4][4];
    float m_i[4], l_i[4];
#pragma unroll
    for(int r=0;r<4;r++){ m_i[r]=-1e30f; l_i[r]=0.f;
#pragma unroll
        for(int c=0;c<4;c++) O[r][c]=0.f; }

    int jmax = 2*qt + 1;
    for(int jt=0;jt<=jmax;jt++){
        __syncthreads();   // prev iter done reading sKP/sV; sQ visible on first iter after this+next
#pragma unroll
        for(int u=0;u<2;u++){
            int s = tid*2+u;            // 512 float4 slots: 32 rows x 16 float4
            int r = s>>4, d = (s&15)*4;
            size_t kb = ((size_t)(b*SEQ + jt*32 + r))*KVD + kvh*HD + d;
            float4 kv = *(const float4*)(g_k + kb);
            sKP[(d+0)*32+r]=kv.x; sKP[(d+1)*32+r]=kv.y;
            sKP[(d+2)*32+r]=kv.z; sKP[(d+3)*32+r]=kv.w;
            *(float4*)&sV[r*64+d] = *(const float4*)(g_v + kb);
        }
        __syncthreads();
        float sv[4][2];
#pragma unroll
        for(int r=0;r<4;r++){ sv[r][0]=0.f; sv[r][1]=0.f; }
        for(int d=0;d<64;d++){
            float a0=sQ[(ty*4+0)*64+d], a1=sQ[(ty*4+1)*64+d];
            float a2=sQ[(ty*4+2)*64+d], a3=sQ[(ty*4+3)*64+d];
            float2 kb = *(const float2*)&sKP[d*32 + tx*2];
            sv[0][0]+=a0*kb.x; sv[0][1]+=a0*kb.y;
            sv[1][0]+=a1*kb.x; sv[1][1]+=a1*kb.y;
            sv[2][0]+=a2*kb.x; sv[2][1]+=a2*kb.y;
            sv[3][0]+=a3*kb.x; sv[3][1]+=a3*kb.y;
        }
        // causal mask (global indices; cheap, branchless per element)
#pragma unroll
        for(int r=0;r<4;r++){
            int qi = qt*64 + ty*4 + r;
#pragma unroll
            for(int c=0;c<2;c++){
                int kj = jt*32 + tx*2 + c;
                if(kj > qi) sv[r][c] = -1e30f;
            }
        }
        // online softmax per row (reduce across the 16 tx lanes)
#pragma unroll
        for(int r=0;r<4;r++){
            float mv = fmaxf(sv[r][0], sv[r][1]);
#pragma unroll
            for(int o=8;o;o>>=1) mv = fmaxf(mv, __shfl_xor_sync(0xffffffffu, mv, o, 16));
            float mn  = fmaxf(m_i[r], mv);
            float fac = __expf(m_i[r] - mn);
            float p0 = __expf(sv[r][0]-mn), p1 = __expf(sv[r][1]-mn);
            sv[r][0]=p0; sv[r][1]=p1;
            float rs = p0 + p1;
#pragma unroll
            for(int o=8;o;o>>=1) rs += __shfl_xor_sync(0xffffffffu, rs, o, 16);
            l_i[r] = l_i[r]*fac + rs;
            m_i[r] = mn;
#pragma unroll
            for(int c=0;c<4;c++) O[r][c] *= fac;
        }
        __syncthreads();  // everyone done reading sKP before overwrite with P
#pragma unroll
        for(int r=0;r<4;r++)
            *(float2*)&sKP[(ty*4+r)*32 + tx*2] = make_float2(sv[r][0], sv[r][1]);
        __syncthreads();
        for(int j=0;j<32;j++){
            float a0=sKP[(ty*4+0)*32+j], a1=sKP[(ty*4+1)*32+j];
            float a2=sKP[(ty*4+2)*32+j], a3=sKP[(ty*4+3)*32+j];
            float4 vb = *(const float4*)&sV[j*64 + tx*4];
            O[0][0]+=a0*vb.x; O[0][1]+=a0*vb.y; O[0][2]+=a0*vb.z; O[0][3]+=a0*vb.w;
            O[1][0]+=a1*vb.x; O[1][1]+=a1*vb.y; O[1][2]+=a1*vb.z; O[1][3]+=a1*vb.w;
            O[2][0]+=a2*vb.x; O[2][1]+=a2*vb.y; O[2][2]+=a2*vb.z; O[2][3]+=a2*vb.w;
            O[3][0]+=a3*vb.x; O[3][1]+=a3*vb.y; O[3][2]+=a3*vb.z; O[3][3]+=a3*vb.w;
        }
    }
#pragma unroll
    for(int r=0;r<4;r++){
        float inv = 1.f / l_i[r];
        float4 o4 = make_float4(O[r][0]*inv, O[r][1]*inv, O[r][2]*inv, O[r][3]*inv);
        *(float4*)(g_ao + ((size_t)(b*SEQ + qt*64 + ty*4 + r))*DIM + h*HD + tx*4) = o4;
    }
}

// ------------------------- MoE routing -------------------------------------
__global__ void zero_k(){
    int i = threadIdx.x;
    if(i < NE){ g_cnt[i]=0; g_scnt[i]=0; }
}

__global__ void route_k(const float* __restrict__ gw){
    int warp = threadIdx.x>>5, lane = threadIdx.x&31;
    int t = blockIdx.x*8 + warp;
    float acc[NE];
#pragma unroll
    for(int e=0;e<NE;e++) acc[e]=0.f;
    const float* xr = g_xn + (size_t)t*DIM;
    for(int i=lane;i<DIM;i+=32){
        float xv = xr[i];
        const float* g = gw + (size_t)i*NE;
#pragma unroll
        for(int e=0;e<NE;e++) acc[e] += xv*g[e];
    }
#pragma unroll
    for(int e=0;e<NE;e++)
#pragma unroll
        for(int o=16;o;o>>=1) acc[e] += __shfl_xor_sync(0xffffffffu, acc[e], o);
    if(lane==0){
        float mx = acc[0];
#pragma unroll
        for(int e=1;e<NE;e++) mx = fmaxf(mx, acc[e]);
        float p[NE];
#pragma unroll
        for(int e=0;e<NE;e++) p[e] = __expf(acc[e]-mx);
        int e0=0;
#pragma unroll
        for(int e=1;e<NE;e++) if(p[e] > p[e0]) e0=e;
        int e1 = (e0==0)?1:0;
#pragma unroll
        for(int e=0;e<NE;e++) if(e!=e0 && p[e] > p[e1]) e1=e;
        float w0=p[e0], w1=p[e1], ws=w0+w1;
        g_tope[t*2]=e0; g_tope[t*2+1]=e1;
        g_topw[t*2]=w0/ws; g_topw[t*2+1]=w1/ws;
        atomicAdd(&g_cnt[e0],1); atomicAdd(&g_cnt[e1],1);
    }
}

__global__ void build_k(){
    if(threadIdx.x || blockIdx.x) return;
    int s=0, nt=0;
    for(int e=0;e<NE;e++){
        g_seg[e]=s;
        int c = g_cnt[e];
        int tiles = (c+127)>>7;
        for(int t2=0;t2<tiles;t2++){
            g_te[nt]=e; g_tp[nt]=s+t2*128;
            int v = c - t2*128;
            g_tv[nt] = v>128 ? 128 : v;
            nt++;
        }
        s += c;
    }
    for(; nt<MAXT; nt++) g_tv[nt]=0;
}

__global__ void scatter_k(){
    int t = blockIdx.x*256 + threadIdx.x;
    if(t >= TT) return;
#pragma unroll
    for(int j=0;j<2;j++){
        int e = g_tope[t*2+j];
        int pos = g_seg[e] + atomicAdd(&g_scnt[e],1);
        g_perm[pos]=t; g_pwgt[pos]=g_topw[t*2+j];
    }
}

// ------------------------- gathered GEMM: x @ w1/w3 ------------------------
__global__ __launch_bounds__(256) void moe13_k(const float* __restrict__ Wbase, int oid){
    int tile = blockIdx.y;
    int valid = g_tv[tile];
    if(valid==0) return;
    int e = g_te[tile], p0 = g_tp[tile];
    const float* Bm = Wbase + (size_t)e*DIM*HID;
    float* Cout = bufsel(oid);
    __shared__ float As[16][128];
    __shared__ float Bs[16][128];
    __shared__ int rowtok[128];
    const int tid = threadIdx.x;
    const int bn = blockIdx.x*128;
    if(tid < 128) rowtok[tid] = (tid < valid) ? g_perm[p0+tid] : -1;
    __syncthreads();
    const int ty = tid>>4, tx = tid&15;
    float acc[8][8];
#pragma unroll
    for(int i=0;i<8;i++)
#pragma unroll
        for(int j=0;j<8;j++) acc[i][j]=0.f;
    for(int k0=0;k0<DIM;k0+=16){
#pragma unroll
        for(int u=0;u<2;u++){
            int s = tid*2+u;
            int r = s>>2, kk = (s&3)*4;
            int tk = rowtok[r];
            float4 av = make_float4(0.f,0.f,0.f,0.f);
            if(tk >= 0) av = *(const float4*)(g_xn + (size_t)tk*DIM + k0 + kk);
            As[kk+0][r]=av.x; As[kk+1][r]=av.y; As[kk+2][r]=av.z; As[kk+3][r]=av.w;
            int br = s>>5, bc = (s&31)*4;
            *(float4*)&Bs[br][bc] = *(const float4*)(Bm + (size_t)(k0+br)*HID + bn + bc);
        }
        __syncthreads();
#pragma unroll
        for(int kk=0;kk<16;kk++){
            float4 a0=*(const float4*)&As[kk][ty*4];
            float4 a1=*(const float4*)&As[kk][ty*4+64];
            float4 b0=*(const float4*)&Bs[kk][tx*4];
            float4 b1=*(const float4*)&Bs[kk][tx*4+64];
            float a[8]={a0.x,a0.y,a0.z,a0.w,a1.x,a1.y,a1.z,a1.w};
            float b[8]={b0.x,b0.y,b0.z,b0.w,b1.x,b1.y,b1.z,b1.w};
#pragma unroll
            for(int i=0;i<8;i++)
#pragma unroll
                for(int j=0;j<8;j++) acc[i][j] += a[i]*b[j];
        }
        __syncthreads();
    }
#pragma unroll
    for(int i=0;i<8;i++){
        int lr = (i<4)? ty*4+i : 64+ty*4+(i-4);
        if(lr >= valid) continue;
        size_t rowoff = (size_t)(p0+lr)*HID + bn;
#pragma unroll
        for(int j=0;j<8;j++){
            int lc = (j<4)? tx*4+j : 64+tx*4+(j-4);
            Cout[rowoff + lc] = acc[i][j];
        }
    }
}

// ------------------------- silu(b1)*b3 -> b1 -------------------------------
__global__ void silu_k(){
    size_t i = ((size_t)blockIdx.x*256 + threadIdx.x)*4;
    float4 a = *(float4*)&g_b1[i];
    float4 b = *(float4*)&g_b3[i];
    a.x = a.x/(1.f+__expf(-a.x))*b.x;
    a.y = a.y/(1.f+__expf(-a.y))*b.y;
    a.z = a.z/(1.f+__expf(-a.z))*b.z;
    a.w = a.w/(1.f+__expf(-a.w))*b.w;
    *(float4*)&g_b1[i] = a;
}

// ------------------------- act @ w2, weighted scatter-add into g_h ---------
__global__ __launch_bounds__(256) void moe2_k(const float* __restrict__ Wbase){
    int tile = blockIdx.y;
    int valid = g_tv[tile];
    if(valid==0) return;
    int e = g_te[tile], p0 = g_tp[tile];
    const float* Bm = Wbase + (size_t)e*HID*DIM;
    __shared__ float As[16][128];
    __shared__ float Bs[16][128];
    const int tid = threadIdx.x;
    const int bn = blockIdx.x*128;
    const int ty = tid>>4, tx = tid&15;
    float acc[8][8];
#pragma unroll
    for(int i=0;i<8;i++)
#pragma unroll
        for(int j=0;j<8;j++) acc[i][j]=0.f;
    for(int k0=0;k0<HID;k0+=16){
#pragma unroll
        for(int u=0;u<2;u++){
            int s = tid*2+u;
            int r = s>>2, kk = (s&3)*4;
            float4 av = make_float4(0.f,0.f,0.f,0.f);
            if(r < valid) av = *(const float4*)(g_b1 + (size_t)(p0+r)*HID + k0 + kk);
            As[kk+0][r]=av.x; As[kk+1][r]=av.y; As[kk+2][r]=av.z; As[kk+3][r]=av.w;
            int br = s>>5, bc = (s&31)*4;
            *(float4*)&Bs[br][bc] = *(const float4*)(Bm + (size_t)(k0+br)*DIM + bn + bc);
        }
        __syncthreads();
#pragma unroll
        for(int kk=0;kk<16;kk++){
            float4 a0=*(const float4*)&As[kk][ty*4];
            float4 a1=*(const float4*)&As[kk][ty*4+64];
            float4 b0=*(const float4*)&Bs[kk][tx*4];
            float4 b1=*(const float4*)&Bs[kk][tx*4+64];
            float a[8]={a0.x,a0.y,a0.z,a0.w,a1.x,a1.y,a1.z,a1.w};
            float b[8]={b0.x,b0.y,b0.z,b0.w,b1.x,b1.y,b1.z,b1.w};
#pragma unroll
            for(int i=0;i<8;i++)
#pragma unroll
                for(int j=0;j<8;j++) acc[i][j] += a[i]*b[j];
        }
        __syncthreads();
    }
#pragma unroll
    for(int i=0;i<8;i++){
        int lr = (i<4)? ty*4+i : 64+ty*4+(i-4);
        if(lr >= valid) continue;
        int p  = p0 + lr;
        int tk = g_perm[p];
        float wf = g_pwgt[p];
        float* hrow = g_h + (size_t)tk*DIM + bn;
#pragma unroll
        for(int j=0;j<8;j++){
            int lc = (j<4)? tx*4+j : 64+tx*4+(j-4);
            atomicAdd(&hrow[lc], wf*acc[i][j]);
        }
    }
}

// ------------------------- host orchestration ------------------------------
extern "C" void kernel_launch(void* const* d_in, const int* in_sizes, int n_in,
                              void* d_out, int out_size)
{
    const int*   tokens    = (const int*)  d_in[0];
    const int*   sp        = (const int*)  d_in[1];
    const float* tok_emb   = (const float*)d_in[2];
    const float* attn_norm = (const float*)d_in[3];
    const float* wq        = (const float*)d_in[4];
    const float* wk        = (const float*)d_in[5];
    const float* wv        = (const float*)d_in[6];
    const float* wo        = (const float*)d_in[7];
    const float* ffn_norm  = (const float*)d_in[8];
    const float* gate      = (const float*)d_in[9];
    const float* w1        = (const float*)d_in[10];
    const float* w2        = (const float*)d_in[11];
    const float* w3        = (const float*)d_in[12];
    const float* normw     = (const float*)d_in[13];
    const float* outw      = (const float*)d_in[14];
    float* out = (float*)d_out;

    embed_k<<<TT*(DIM/4)/256, 256>>>(tokens, tok_emb);

    for(int l=0;l<NL;l++){
        rms_k<<<TT,256>>>(attn_norm + (size_t)l*DIM);
        sgemm_k<0><<<dim3(DIM/128, TT/128), 256>>>(1, wq + (size_t)l*DIM*DIM, nullptr, 2, TT, DIM, DIM);
        sgemm_k<0><<<dim3(KVD/128, TT/128), 256>>>(1, wk + (size_t)l*DIM*KVD, nullptr, 3, TT, KVD, DIM);
        sgemm_k<0><<<dim3(KVD/128, TT/128), 256>>>(1, wv + (size_t)l*DIM*KVD, nullptr, 4, TT, KVD, DIM);
        rope_k<<<TT*NH*(HD/2)/256, 256>>>(2, NH, sp);
        rope_k<<<TT*NKV*(HD/2)/256, 256>>>(3, NKV, sp);
        attn_k<<<dim3(SEQ/64, NH, NBATCH), 256>>>();
        sgemm_k<1><<<dim3(DIM/128, TT/128), 256>>>(5, wo + (size_t)l*DIM*DIM, nullptr, 0, TT, DIM, DIM);

        rms_k<<<TT,256>>>(ffn_norm + (size_t)l*DIM);
        zero_k<<<1,32>>>();
        route_k<<<TT/8,256>>>(gate + (size_t)l*DIM*NE);
        build_k<<<1,1>>>();
        scatter_k<<<TT/256,256>>>();
        moe13_k<<<dim3(HID/128, MAXT), 256>>>(w1 + (size_t)l*NE*DIM*HID, 6);
        moe13_k<<<dim3(HID/128, MAXT), 256>>>(w3 + (size_t)l*NE*DIM*HID, 7);
        silu_k<<<(TT*2*HID/4)/256, 256>>>();
        moe2_k<<<dim3(DIM/128, MAXT), 256>>>(w2 + (size_t)l*NE*HID*DIM);
    }

    rms_k<<<TT,256>>>(normw);
    sgemm_k<0><<<dim3(VOCAB/128, TT/128), 256>>>(1, outw, out, -1, TT, VOCAB, DIM);
}